// round 6
// baseline (speedup 1.0000x reference)
#include <cuda_runtime.h>

#define TT 512
#define BB 128
#define DD 50
#define HH 200
#define KK 25
#define GP 832      // padded 4H = 13*64, gate-interleaved (j = 4*u + gate)
#define NJT 13
#define TB 32       // lstm batch tile
#define TJ 64       // j tile
#define XTB 64      // xw_gemm row tile
#define XKC 50      // xw_gemm k chunk
#define ASTR 66     // xw_gemm As row stride (padded)

typedef unsigned long long ull;

// ---------------- device scratch (static; no allocation allowed) ----------------
__device__ float g_xw[(size_t)2 * TT * BB * GP];        // [dir][t][b][j']
__device__ float g_hcat0[(size_t)TT * BB * 2 * HH];     // layer0 output [t][b][2H]
__device__ float g_hcat1[(size_t)TT * BB * 2 * HH];     // layer1 output
__device__ float g_hT[2][2][HH][BB];                    // [buf][dir][u][b] transposed h
__device__ unsigned g_bar[8 * 32];                      // per-(dir,btile) counters, 128B apart
__device__ float g_em[(size_t)TT * BB * KK];
__device__ float g_emexp[(size_t)TT * BB * KK];
__device__ float g_wih0t[2 * DD * GP];                  // [d][i<50][j']
__device__ float g_wih1t[2 * 2 * HH * GP];              // [d][i<400][j']
__device__ float g_whht[2 * 2 * HH * GP];               // [layer][d][h][j']
__device__ float g_bsum[2 * 2 * GP];                    // [layer][d][j']
__device__ float g_crf[BB];

// ---------------- packed f32x2 helpers (Blackwell FFMA2) ----------------
static __device__ __forceinline__ ull pk2(float x, float y) {
    ull r; asm("mov.b64 %0, {%1, %2};" : "=l"(r) : "f"(x), "f"(y)); return r;
}
static __device__ __forceinline__ void upk2(ull v, float& x, float& y) {
    asm("mov.b64 {%0, %1}, %2;" : "=f"(x), "=f"(y) : "l"(v));
}
static __device__ __forceinline__ ull f2fma(ull a, ull b, ull c) {
    ull d; asm("fma.rn.f32x2 %0, %1, %2, %3;" : "=l"(d) : "l"(a), "l"(b), "l"(c)); return d;
}
static __device__ __forceinline__ ull f2add(ull a, ull b) {
    ull d; asm("add.rn.f32x2 %0, %1, %2;" : "=l"(d) : "l"(a), "l"(b)); return d;
}
static __device__ __forceinline__ float sigf(float x) {
    return __fdividef(1.f, 1.f + __expf(-x));
}
static __device__ __forceinline__ float tanhfast(float x) {
    return 2.f * __fdividef(1.f, 1.f + __expf(-2.f * x)) - 1.f;
}

// ---------------- cp.async helpers ----------------
#define CP16(dst_u32, src_ptr) \
    asm volatile("cp.async.cg.shared.global [%0], [%1], 16;\n" :: "r"(dst_u32), "l"(src_ptr))
#define CP4(dst_u32, src_ptr) \
    asm volatile("cp.async.ca.shared.global [%0], [%1], 4;\n" :: "r"(dst_u32), "l"(src_ptr))
#define CPCOMMIT asm volatile("cp.async.commit_group;\n" ::)
#define CPWAIT(n) asm volatile("cp.async.wait_group %0;\n" :: "n"(n))

// ---------------- prep: transpose + gate-permute + pad weights, bias sums ----------------
__global__ void prep_kernel(const float* __restrict__ b_l0, const float* __restrict__ b_l1,
                            const float* __restrict__ wih0, const float* __restrict__ wih1,
                            const float* __restrict__ whh0, const float* __restrict__ whh1) {
    int idx = blockIdx.x * blockDim.x + threadIdx.x;
    const int S0 = 2 * 2 * GP;
    const int S1 = 2 * DD * GP;
    const int S2 = 2 * 2 * HH * GP;
    const int S3 = 2 * 2 * HH * GP;
    if (idx < S0) {
        int j = idx % GP; int d = (idx / GP) & 1; int l = idx / (GP * 2);
        int u = j >> 2, g = j & 3; float v = 0.f;
        if (u < HH) {
            int col = g * HH + u;
            const float* bl = l ? b_l1 : b_l0;
            v = bl[(d * 2 + 0) * 4 * HH + col] + bl[(d * 2 + 1) * 4 * HH + col];
        }
        g_bsum[idx] = v; return;
    }
    idx -= S0;
    if (idx < S1) {
        int j = idx % GP; int i = (idx / GP) % DD; int d = idx / (GP * DD);
        int u = j >> 2, g = j & 3; float v = 0.f;
        if (u < HH) v = wih0[(size_t)(d * 4 * HH + g * HH + u) * DD + i];
        g_wih0t[idx] = v; return;
    }
    idx -= S1;
    if (idx < S2) {
        int j = idx % GP; int i = (idx / GP) % (2 * HH); int d = idx / (GP * 2 * HH);
        int u = j >> 2, g = j & 3; float v = 0.f;
        if (u < HH) v = wih1[(size_t)(d * 4 * HH + g * HH + u) * (2 * HH) + i];
        g_wih1t[idx] = v; return;
    }
    idx -= S2;
    if (idx < S3) {
        int j = idx % GP; int h = (idx / GP) % HH; int d = (idx / (GP * HH)) & 1;
        int l = idx / (GP * HH * 2);
        int u = j >> 2, g = j & 3; float v = 0.f;
        const float* w = l ? whh1 : whh0;
        if (u < HH) v = w[(size_t)(d * 4 * HH + g * HH + u) * HH + h];
        g_whht[idx] = v; return;
    }
}

__global__ void bar_reset() {
    g_bar[threadIdx.x] = 0u;
}

// ---------------- input-projection GEMM (mode0: emb gather K=50; mode1: hcat0 K=400) ----
// Warp owns 8 cols x 64 rows; lane = 4 consecutive cols x 4 rows (2 row pairs).
// Double-buffered cp.async pipeline over k chunks.
__global__ void __launch_bounds__(256) xw_gemm(const int* __restrict__ xidx,
                                               const float* __restrict__ emb, int mode) {
    const int Kdim = mode ? 2 * HH : DD;
    const float* __restrict__ Wt = mode ? g_wih1t : g_wih0t;
    const int d = blockIdx.z;
    const float* __restrict__ bs = g_bsum + (size_t)((mode ? 2 : 0) + d) * GP;
    const int jbase = blockIdx.x * TJ;
    const int rbase = blockIdx.y * XTB;
    const int tid = threadIdx.x;
    const int w = tid >> 5, l = tid & 31;
    const int c0 = w * 8 + (l >> 4) * 4;     // local col base (all 4 gates of one unit)
    const int r0 = 2 * (l & 15);             // local row pair base (rows r0, r0+1, r0+32, r0+33)
    const float* __restrict__ Wd = Wt + (size_t)d * Kdim * GP;

    extern __shared__ __align__(16) float xsm[];
    float* Asb[2] = {xsm, xsm + XKC * ASTR};                       // 2 x 3300
    float* Wsb[2] = {xsm + 2 * XKC * ASTR, xsm + 2 * XKC * ASTR + XKC * TJ}; // 2 x 3200
    unsigned asu[2], wsu[2];
    asu[0] = (unsigned)__cvta_generic_to_shared(Asb[0]);
    asu[1] = (unsigned)__cvta_generic_to_shared(Asb[1]);
    wsu[0] = (unsigned)__cvta_generic_to_shared(Wsb[0]);
    wsu[1] = (unsigned)__cvta_generic_to_shared(Wsb[1]);

    ull acc[4][2];
    #pragma unroll
    for (int a = 0; a < 4; a++) { acc[a][0] = 0ull; acc[a][1] = 0ull; }

    auto issue_tile = [&](int buf, int k0) {
        unsigned ab = asu[buf], wb = wsu[buf];
        // A tile: transpose during load, 4B cp.async
        for (int e = tid; e < XKC * XTB; e += 256) {
            int r = e / XKC, kk = e - r * XKC;
            const float* src;
            if (mode) {
                src = &g_hcat0[(size_t)(rbase + r) * (2 * HH) + k0 + kk];
            } else {
                int row = rbase + r;
                int t = row >> 7, b = row & 127;
                src = &emb[(size_t)xidx[b * TT + t] * DD + kk];
            }
            CP4(ab + (unsigned)((kk * ASTR + r) * 4), src);
        }
        // W tile: 16B cp.async
        for (int e = tid; e < XKC * 16; e += 256) {
            int kk = e >> 4, c = (e & 15) * 4;
            CP16(wb + (unsigned)((kk * TJ + c) * 4),
                 Wd + (size_t)(k0 + kk) * GP + jbase + c);
        }
        CPCOMMIT;
    };

    const int niter = Kdim / XKC;
    issue_tile(0, 0);
    for (int it = 0; it < niter; it++) {
        if (it + 1 < niter) {
            issue_tile((it + 1) & 1, (it + 1) * XKC);
            CPWAIT(1);
        } else {
            CPWAIT(0);
        }
        __syncthreads();
        const float* As = Asb[it & 1];
        const float* Ws = Wsb[it & 1];
        #pragma unroll 10
        for (int kk = 0; kk < XKC; kk++) {
            float2 av0 = *(const float2*)&As[kk * ASTR + r0];
            float2 av1 = *(const float2*)&As[kk * ASTR + r0 + 32];
            float4 wv = *(const float4*)&Ws[kk * TJ + c0];
            ull w0 = pk2(wv.x, wv.y), w1 = pk2(wv.z, wv.w);
            ull d0 = pk2(av0.x, av0.x), d1 = pk2(av0.y, av0.y);
            ull d2 = pk2(av1.x, av1.x), d3 = pk2(av1.y, av1.y);
            acc[0][0] = f2fma(d0, w0, acc[0][0]); acc[0][1] = f2fma(d0, w1, acc[0][1]);
            acc[1][0] = f2fma(d1, w0, acc[1][0]); acc[1][1] = f2fma(d1, w1, acc[1][1]);
            acc[2][0] = f2fma(d2, w0, acc[2][0]); acc[2][1] = f2fma(d2, w1, acc[2][1]);
            acc[3][0] = f2fma(d3, w0, acc[3][0]); acc[3][1] = f2fma(d3, w1, acc[3][1]);
        }
        __syncthreads();
    }
    float* __restrict__ Cd = g_xw + (size_t)d * TT * BB * GP;
    float4 bv = *(const float4*)(bs + jbase + c0);
    const int rows[4] = {r0, r0 + 1, r0 + 32, r0 + 33};
    #pragma unroll
    for (int a = 0; a < 4; a++) {
        float v0, v1, v2, v3;
        upk2(acc[a][0], v0, v1); upk2(acc[a][1], v2, v3);
        *(float4*)&Cd[(size_t)(rbase + rows[a]) * GP + jbase + c0] =
            make_float4(v0 + bv.x, v1 + bv.y, v2 + bv.z, v3 + bv.w);
    }
}

// ---------------- persistent LSTM: one GEMM chunk (40 k) ----------------
template<int C>
static __device__ __forceinline__ void lstm_chunk(const float* __restrict__ Ws,
                                                  const float* __restrict__ As,
                                                  int c0, int r0,
                                                  ull& A0, ull& A1, ull& B0, ull& B1) {
    CPWAIT(4 - C);
    __syncthreads();
    const float* ap = As + C * 40 * TB + r0;
    const float* wp = Ws + C * 40 * TJ + c0;
    #pragma unroll 10
    for (int kk = 0; kk < 40; kk++) {
        float2 av = *(const float2*)(ap + kk * TB);
        float4 wv = *(const float4*)(wp + kk * TJ);
        ull w0 = pk2(wv.x, wv.y), w1 = pk2(wv.z, wv.w);
        ull a0 = pk2(av.x, av.x), a1 = pk2(av.y, av.y);
        A0 = f2fma(a0, w0, A0); A1 = f2fma(a0, w1, A1);
        B0 = f2fma(a1, w0, B0); B1 = f2fma(a1, w1, B1);
    }
}

// ---------------- persistent bidirectional LSTM layer ----------------
// grid (13, 4, 2): j-tile (16 units), b-tile (32 batch), direction. 104 blocks, all resident.
// Warp owns 8 cols x 32 rows; lane = 4 cols (all gates of unit u) x 2 rows. No shuffles needed.
__global__ void __launch_bounds__(256, 1) lstm_persist(int layer) {
    const int jt = blockIdx.x, bt = blockIdx.y, d = blockIdx.z;
    const int tid = threadIdx.x;
    const int w = tid >> 5, l = tid & 31;
    const int jbase = jt * TJ, bbase = bt * TB;
    const int grp = (d * 4 + bt) * 32;
    const int c0 = w * 8 + (l >> 4) * 4;     // local col base (4 gates of one unit)
    const int u = jt * 16 + (c0 >> 2);       // global hidden unit
    const int r0 = 2 * (l & 15);             // local batch-row pair
    const float* __restrict__ Wg = g_whht + (size_t)(layer * 2 + d) * HH * GP;
    const float* __restrict__ xwd = g_xw + (size_t)d * TT * BB * GP;
    float* __restrict__ hcat = layer ? g_hcat1 : g_hcat0;

    extern __shared__ __align__(16) float smem[];
    float* Ws = smem;                 // [200][64] resident weights, 51.2KB
    float* As = smem + HH * TJ;       // [200][32] h tile, 25.6KB
    unsigned wsb = (unsigned)__cvta_generic_to_shared(Ws);
    unsigned asb = (unsigned)__cvta_generic_to_shared(As);

    // ---- load Whh tile once, resident for all 512 steps
    for (int e = tid; e < (HH * TJ) / 4; e += 256) {
        int kk = e >> 4, cc = (e & 15) * 4;
        CP16(wsb + (unsigned)((kk * TJ + cc) * 4), Wg + (size_t)kk * GP + jbase + cc);
    }
    CPCOMMIT; CPWAIT(0);
    __syncthreads();

    float cc0 = 0.f, cc1 = 0.f;   // cell state: rows r0, r0+1 of unit u

    for (int s = 0; s < TT; s++) {
        const int t = d ? (TT - 1 - s) : s;

        // prefetch xw(t) for this lane's 2 rows x 4 cols (independent of h)
        const float* xwt = xwd + ((size_t)t * BB + bbase) * GP + jbase;
        float4 xa = *(const float4*)(xwt + (size_t)r0 * GP + c0);
        float4 xb = *(const float4*)(xwt + (size_t)(r0 + 1) * GP + c0);

        ull A0 = 0ull, A1 = 0ull, B0 = 0ull, B1 = 0ull;

        if (s > 0) {
            // wait for h(s-1) from all 13 j-tile blocks of this (dir,b-tile)
            if (tid == 0) {
                const unsigned tgt = 13u * (unsigned)s;
                unsigned v;
                do {
                    asm volatile("ld.acquire.gpu.global.u32 %0, [%1];"
                                 : "=r"(v) : "l"(g_bar + grp) : "memory");
                } while (v < tgt);
            }
            __syncthreads();

            // issue h-tile in 5 chunks of 40 k (cp.async.cg: L2-coherent)
            const float* hTr = &g_hT[s & 1][d][0][0];
            #pragma unroll
            for (int c = 0; c < 5; c++) {
                for (int e = tid; e < 320; e += 256) {
                    int kk = c * 40 + (e >> 3), seg = e & 7;
                    CP16(asb + (unsigned)((kk * TB + seg * 4) * 4),
                         hTr + (size_t)kk * BB + bbase + seg * 4);
                }
                CPCOMMIT;
            }
            lstm_chunk<0>(Ws, As, c0, r0, A0, A1, B0, B1);
            lstm_chunk<1>(Ws, As, c0, r0, A0, A1, B0, B1);
            lstm_chunk<2>(Ws, As, c0, r0, A0, A1, B0, B1);
            lstm_chunk<3>(Ws, As, c0, r0, A0, A1, B0, B1);
            lstm_chunk<4>(Ws, As, c0, r0, A0, A1, B0, B1);
        }

        // add xw: A-accs are row r0, B-accs row r0+1; pairs (i,f) and (g,o)
        A0 = f2add(A0, pk2(xa.x, xa.y)); A1 = f2add(A1, pk2(xa.z, xa.w));
        B0 = f2add(B0, pk2(xb.x, xb.y)); B1 = f2add(B1, pk2(xb.z, xb.w));

        float gi0, gf0, gg0, go0, gi1, gf1, gg1, go1;
        upk2(A0, gi0, gf0); upk2(A1, gg0, go0);
        upk2(B0, gi1, gf1); upk2(B1, gg1, go1);

        float cn0 = sigf(gf0) * cc0 + sigf(gi0) * tanhfast(gg0);
        float hn0 = sigf(go0) * tanhfast(cn0);
        float cn1 = sigf(gf1) * cc1 + sigf(gi1) * tanhfast(gg1);
        float hn1 = sigf(go1) * tanhfast(cn1);
        cc0 = cn0; cc1 = cn1;

        // publish h (group-critical), release-arrive, then hcat store
        if (u < HH) {
            *(float2*)&g_hT[(s & 1) ^ 1][d][u][bbase + r0] = make_float2(hn0, hn1);
        }
        __syncthreads();
        if (tid == 0) {
            asm volatile("red.release.gpu.global.add.u32 [%0], %1;"
                         :: "l"(g_bar + grp), "r"(1u) : "memory");
        }
        if (u < HH) {
            size_t hb = ((size_t)t * BB + (bbase + r0)) * (2 * HH) + d * HH + u;
            hcat[hb] = hn0;
            hcat[hb + 2 * HH] = hn1;
        }
    }
}

// ---------------- emissions: em = hcat1 @ lin_w^T + lin_b, plus exp(em) ----------------
__global__ void em_kernel(const float* __restrict__ lin_w, const float* __restrict__ lin_b) {
    int row = blockIdx.x * 8 + (threadIdx.x >> 5);
    int k = threadIdx.x & 31;
    if (k >= KK) return;
    const float4* a4 = (const float4*)(g_hcat1 + (size_t)row * (2 * HH));
    const float4* w4 = (const float4*)(lin_w + (size_t)k * (2 * HH));
    float s0 = 0, s1 = 0, s2 = 0, s3 = 0;
    #pragma unroll 4
    for (int i = 0; i < (2 * HH) / 4; i++) {
        float4 av = a4[i], wv = w4[i];
        s0 += av.x * wv.x; s1 += av.y * wv.y; s2 += av.z * wv.z; s3 += av.w * wv.w;
    }
    float acc = (s0 + s1) + (s2 + s3) + lin_b[k];
    g_em[(size_t)row * KK + k] = acc;
    g_emexp[(size_t)row * KK + k] = __expf(acc);
}

// ---------------- CRF: numerator + linear-domain forward algorithm ----------------
__global__ void crf_kernel(const int* __restrict__ y, const float* __restrict__ start,
                           const float* __restrict__ endw, const float* __restrict__ trans) {
    int b = blockIdx.x;
    int lane = threadIdx.x;
    __shared__ float Me[KK][KK];
    __shared__ float Tr[KK][KK];
    __shared__ float p[KK];
    for (int e = lane; e < KK * KK; e += 32) {
        float tv = trans[e];
        Tr[e / KK][e % KK] = tv;
        Me[e / KK][e % KK] = __expf(tv);
    }
    __syncwarp();
    float num = 0.f;
    for (int t = lane; t < TT; t += 32) {
        int yt = y[b * TT + t];
        float e = g_em[((size_t)t * BB + b) * KK + yt];
        if (t == 0) num += start[yt] + e;
        else {
            int yp = y[b * TT + t - 1];
            num += Tr[yp][yt] + e;
        }
        if (t == TT - 1) num += endw[yt];
    }
    for (int o = 16; o; o >>= 1) num += __shfl_down_sync(0xffffffffu, num, o);
    num = __shfl_sync(0xffffffffu, num, 0);
    float myp = 0.f;
    if (lane < KK) myp = __expf(start[lane] + g_em[(size_t)b * KK + lane]);
    float ssum = myp;
    for (int o = 16; o; o >>= 1) ssum += __shfl_down_sync(0xffffffffu, ssum, o);
    ssum = __shfl_sync(0xffffffffu, ssum, 0);
    float logZ = logf(ssum);
    if (lane < KK) p[lane] = myp / ssum;
    __syncwarp();
    for (int t = 1; t < TT; t++) {
        float acc = 0.f;
        if (lane < KK) {
            #pragma unroll 5
            for (int k1 = 0; k1 < KK; k1++) acc += p[k1] * Me[k1][lane];
            acc *= g_emexp[((size_t)t * BB + b) * KK + lane];
        }
        float s = acc;
        for (int o = 16; o; o >>= 1) s += __shfl_down_sync(0xffffffffu, s, o);
        s = __shfl_sync(0xffffffffu, s, 0);
        logZ += logf(s);
        float is = 1.f / s;
        __syncwarp();
        if (lane < KK) p[lane] = acc * is;
        __syncwarp();
    }
    float fin = (lane < KK) ? p[lane] * __expf(endw[lane]) : 0.f;
    for (int o = 16; o; o >>= 1) fin += __shfl_down_sync(0xffffffffu, fin, o);
    if (lane == 0) {
        float den = logZ + logf(fin);
        g_crf[b] = num - den;
    }
}

__global__ void final_reduce(float* __restrict__ out) {
    __shared__ float sm[BB];
    int tid = threadIdx.x;
    sm[tid] = g_crf[tid];
    __syncthreads();
    for (int st = 64; st > 0; st >>= 1) {
        if (tid < st) sm[tid] += sm[tid + st];
        __syncthreads();
    }
    if (tid == 0) out[0] = sm[0];
}

// ---------------- launch ----------------
extern "C" void kernel_launch(void* const* d_in, const int* in_sizes, int n_in,
                              void* d_out, int out_size) {
    const int* x = (const int*)d_in[0];
    const int* y = (const int*)d_in[1];
    // d_in[2] = mask (all ones by construction) — unused
    const float* emb = (const float*)d_in[3];
    const float* wih0 = (const float*)d_in[4];
    const float* whh0 = (const float*)d_in[5];
    const float* b0 = (const float*)d_in[6];
    const float* wih1 = (const float*)d_in[7];
    const float* whh1 = (const float*)d_in[8];
    const float* b1 = (const float*)d_in[9];
    const float* lin_w = (const float*)d_in[10];
    const float* lin_b = (const float*)d_in[11];
    const float* crf_s = (const float*)d_in[12];
    const float* crf_e = (const float*)d_in[13];
    const float* crf_t = (const float*)d_in[14];
    float* out = (float*)d_out;

    const int lstm_smem = (HH * TJ + HH * TB) * 4;                 // 76800 bytes
    const int xw_smem = (2 * XKC * ASTR + 2 * XKC * TJ) * 4;       // 52000 bytes
    cudaFuncSetAttribute(lstm_persist, cudaFuncAttributeMaxDynamicSharedMemorySize, lstm_smem);
    cudaFuncSetAttribute(xw_gemm, cudaFuncAttributeMaxDynamicSharedMemorySize, xw_smem);

    prep_kernel<<<5538, 256>>>(b0, b1, wih0, wih1, whh0, whh1);

    // layer 0: input projection (emb gather, K=50) then persistent recurrence
    xw_gemm<<<dim3(NJT, (TT * BB) / XTB, 2), 256, xw_smem>>>(x, emb, 0);
    bar_reset<<<1, 256>>>();
    lstm_persist<<<dim3(NJT, BB / TB, 2), 256, lstm_smem>>>(0);

    // layer 1: input projection (K=400) then persistent recurrence
    xw_gemm<<<dim3(NJT, (TT * BB) / XTB, 2), 256, xw_smem>>>(x, emb, 1);
    bar_reset<<<1, 256>>>();
    lstm_persist<<<dim3(NJT, BB / TB, 2), 256, lstm_smem>>>(1);

    em_kernel<<<(TT * BB) / 8, 256>>>(lin_w, lin_b);
    crf_kernel<<<BB, 32>>>(y, crf_s, crf_e, crf_t);
    final_reduce<<<1, BB>>>(out);
}

// round 10
// speedup vs baseline: 1.0447x; 1.0447x over previous
#include <cuda_runtime.h>

#define TT 512
#define BB 128
#define DD 50
#define HH 200
#define KK 25
#define GP 832      // padded 4H = 13*64, gate-interleaved (j = 4*u + gate)
#define NJT 13
#define LTB 16      // lstm batch tile (per chain)
#define TJ 64       // j tile
#define XTB 64      // xw_gemm row tile
#define XKC 50      // xw_gemm k chunk
#define ASTR 66     // xw_gemm As row stride (padded)

typedef unsigned long long ull;

// ---------------- device scratch (static; no allocation allowed) ----------------
__device__ float g_xw[(size_t)2 * TT * BB * GP];        // [dir][t][b][j']
__device__ float g_hcat0[(size_t)TT * BB * 2 * HH];     // layer0 output [t][b][2H]
__device__ float g_hcat1[(size_t)TT * BB * 2 * HH];     // layer1 output
__device__ float g_h2[2][2][8][HH][LTB];                // [buf][dir][btile][u][b16] contiguous per (dir,btile)
__device__ unsigned g_bar[16 * 32];                     // per-(dir,btile) counters, 128B apart
__device__ float g_em[(size_t)TT * BB * KK];
__device__ float g_emexp[(size_t)TT * BB * KK];
__device__ float g_wih0t[2 * DD * GP];                  // [d][i<50][j']
__device__ float g_wih1t[2 * 2 * HH * GP];              // [d][i<400][j']
__device__ float g_whht[2 * 2 * HH * GP];               // [layer][d][h][j']
__device__ float g_bsum[2 * 2 * GP];                    // [layer][d][j']
__device__ float g_crf[BB];

// ---------------- packed f32x2 helpers (Blackwell FFMA2) ----------------
static __device__ __forceinline__ ull pk2(float x, float y) {
    ull r; asm("mov.b64 %0, {%1, %2};" : "=l"(r) : "f"(x), "f"(y)); return r;
}
static __device__ __forceinline__ void upk2(ull v, float& x, float& y) {
    asm("mov.b64 {%0, %1}, %2;" : "=f"(x), "=f"(y) : "l"(v));
}
static __device__ __forceinline__ ull f2fma(ull a, ull b, ull c) {
    ull d; asm("fma.rn.f32x2 %0, %1, %2, %3;" : "=l"(d) : "l"(a), "l"(b), "l"(c)); return d;
}
static __device__ __forceinline__ ull f2add(ull a, ull b) {
    ull d; asm("add.rn.f32x2 %0, %1, %2;" : "=l"(d) : "l"(a), "l"(b)); return d;
}
static __device__ __forceinline__ float sigf(float x) {
    return __fdividef(1.f, 1.f + __expf(-x));
}
static __device__ __forceinline__ float tanhfast(float x) {
    return 2.f * __fdividef(1.f, 1.f + __expf(-2.f * x)) - 1.f;
}

// ---------------- cp.async / mbarrier helpers ----------------
#define CP16(dst_u32, src_ptr) \
    asm volatile("cp.async.cg.shared.global [%0], [%1], 16;\n" :: "r"(dst_u32), "l"(src_ptr))
#define CP4(dst_u32, src_ptr) \
    asm volatile("cp.async.ca.shared.global [%0], [%1], 4;\n" :: "r"(dst_u32), "l"(src_ptr))
#define CPCOMMIT asm volatile("cp.async.commit_group;\n" ::)
#define CPWAIT(n) asm volatile("cp.async.wait_group %0;\n" :: "n"(n))

static __device__ __forceinline__ void mbar_init(unsigned mbar, unsigned cnt) {
    asm volatile("mbarrier.init.shared.b64 [%0], %1;" :: "r"(mbar), "r"(cnt) : "memory");
}
static __device__ __forceinline__ void mbar_expect_tx(unsigned mbar, unsigned tx) {
    asm volatile("mbarrier.arrive.expect_tx.shared.b64 _, [%0], %1;" :: "r"(mbar), "r"(tx) : "memory");
}
static __device__ __forceinline__ void bulk_g2s(unsigned dst, const void* src, unsigned bytes, unsigned mbar) {
    asm volatile("cp.async.bulk.shared::cluster.global.mbarrier::complete_tx::bytes [%0], [%1], %2, [%3];"
                 :: "r"(dst), "l"(src), "r"(bytes), "r"(mbar) : "memory");
}
static __device__ __forceinline__ void mbar_wait(unsigned mbar, unsigned phase) {
    asm volatile(
        "{\n\t.reg .pred P;\n"
        "W%=:\n\t"
        "mbarrier.try_wait.parity.acquire.cta.shared::cta.b64 P, [%0], %1, 0x989680;\n\t"
        "@!P bra W%=;\n\t}"
        :: "r"(mbar), "r"(phase) : "memory");
}

// ---------------- prep: transpose + gate-permute + pad weights, bias sums ----------------
__global__ void prep_kernel(const float* __restrict__ b_l0, const float* __restrict__ b_l1,
                            const float* __restrict__ wih0, const float* __restrict__ wih1,
                            const float* __restrict__ whh0, const float* __restrict__ whh1) {
    int idx = blockIdx.x * blockDim.x + threadIdx.x;
    const int S0 = 2 * 2 * GP;
    const int S1 = 2 * DD * GP;
    const int S2 = 2 * 2 * HH * GP;
    const int S3 = 2 * 2 * HH * GP;
    if (idx < S0) {
        int j = idx % GP; int d = (idx / GP) & 1; int l = idx / (GP * 2);
        int u = j >> 2, g = j & 3; float v = 0.f;
        if (u < HH) {
            int col = g * HH + u;
            const float* bl = l ? b_l1 : b_l0;
            v = bl[(d * 2 + 0) * 4 * HH + col] + bl[(d * 2 + 1) * 4 * HH + col];
        }
        g_bsum[idx] = v; return;
    }
    idx -= S0;
    if (idx < S1) {
        int j = idx % GP; int i = (idx / GP) % DD; int d = idx / (GP * DD);
        int u = j >> 2, g = j & 3; float v = 0.f;
        if (u < HH) v = wih0[(size_t)(d * 4 * HH + g * HH + u) * DD + i];
        g_wih0t[idx] = v; return;
    }
    idx -= S1;
    if (idx < S2) {
        int j = idx % GP; int i = (idx / GP) % (2 * HH); int d = idx / (GP * 2 * HH);
        int u = j >> 2, g = j & 3; float v = 0.f;
        if (u < HH) v = wih1[(size_t)(d * 4 * HH + g * HH + u) * (2 * HH) + i];
        g_wih1t[idx] = v; return;
    }
    idx -= S2;
    if (idx < S3) {
        int j = idx % GP; int h = (idx / GP) % HH; int d = (idx / (GP * HH)) & 1;
        int l = idx / (GP * HH * 2);
        int u = j >> 2, g = j & 3; float v = 0.f;
        const float* w = l ? whh1 : whh0;
        if (u < HH) v = w[(size_t)(d * 4 * HH + g * HH + u) * HH + h];
        g_whht[idx] = v; return;
    }
}

__global__ void bar_reset() {
    g_bar[threadIdx.x] = 0u;
}

// ---------------- input-projection GEMM (mode0: emb gather K=50; mode1: hcat0 K=400) ----
__global__ void __launch_bounds__(256) xw_gemm(const int* __restrict__ xidx,
                                               const float* __restrict__ emb, int mode) {
    const int Kdim = mode ? 2 * HH : DD;
    const float* __restrict__ Wt = mode ? g_wih1t : g_wih0t;
    const int d = blockIdx.z;
    const float* __restrict__ bs = g_bsum + (size_t)((mode ? 2 : 0) + d) * GP;
    const int jbase = blockIdx.x * TJ;
    const int rbase = blockIdx.y * XTB;
    const int tid = threadIdx.x;
    const int w = tid >> 5, l = tid & 31;
    const int c0 = w * 8 + (l >> 4) * 4;
    const int r0 = 2 * (l & 15);
    const float* __restrict__ Wd = Wt + (size_t)d * Kdim * GP;

    extern __shared__ __align__(16) float xsm[];
    float* Asb[2] = {xsm, xsm + XKC * ASTR};
    float* Wsb[2] = {xsm + 2 * XKC * ASTR, xsm + 2 * XKC * ASTR + XKC * TJ};
    unsigned asu[2], wsu[2];
    asu[0] = (unsigned)__cvta_generic_to_shared(Asb[0]);
    asu[1] = (unsigned)__cvta_generic_to_shared(Asb[1]);
    wsu[0] = (unsigned)__cvta_generic_to_shared(Wsb[0]);
    wsu[1] = (unsigned)__cvta_generic_to_shared(Wsb[1]);

    ull acc[4][2];
    #pragma unroll
    for (int a = 0; a < 4; a++) { acc[a][0] = 0ull; acc[a][1] = 0ull; }

    auto issue_tile = [&](int buf, int k0) {
        unsigned ab = asu[buf], wb = wsu[buf];
        for (int e = tid; e < XKC * XTB; e += 256) {
            int r = e / XKC, kk = e - r * XKC;
            const float* src;
            if (mode) {
                src = &g_hcat0[(size_t)(rbase + r) * (2 * HH) + k0 + kk];
            } else {
                int row = rbase + r;
                int t = row >> 7, b = row & 127;
                src = &emb[(size_t)xidx[b * TT + t] * DD + kk];
            }
            CP4(ab + (unsigned)((kk * ASTR + r) * 4), src);
        }
        for (int e = tid; e < XKC * 16; e += 256) {
            int kk = e >> 4, c = (e & 15) * 4;
            CP16(wb + (unsigned)((kk * TJ + c) * 4),
                 Wd + (size_t)(k0 + kk) * GP + jbase + c);
        }
        CPCOMMIT;
    };

    const int niter = Kdim / XKC;
    issue_tile(0, 0);
    for (int it = 0; it < niter; it++) {
        if (it + 1 < niter) {
            issue_tile((it + 1) & 1, (it + 1) * XKC);
            CPWAIT(1);
        } else {
            CPWAIT(0);
        }
        __syncthreads();
        const float* As = Asb[it & 1];
        const float* Ws = Wsb[it & 1];
        #pragma unroll 10
        for (int kk = 0; kk < XKC; kk++) {
            float2 av0 = *(const float2*)&As[kk * ASTR + r0];
            float2 av1 = *(const float2*)&As[kk * ASTR + r0 + 32];
            float4 wv = *(const float4*)&Ws[kk * TJ + c0];
            ull w0 = pk2(wv.x, wv.y), w1 = pk2(wv.z, wv.w);
            ull d0 = pk2(av0.x, av0.x), d1 = pk2(av0.y, av0.y);
            ull d2 = pk2(av1.x, av1.x), d3 = pk2(av1.y, av1.y);
            acc[0][0] = f2fma(d0, w0, acc[0][0]); acc[0][1] = f2fma(d0, w1, acc[0][1]);
            acc[1][0] = f2fma(d1, w0, acc[1][0]); acc[1][1] = f2fma(d1, w1, acc[1][1]);
            acc[2][0] = f2fma(d2, w0, acc[2][0]); acc[2][1] = f2fma(d2, w1, acc[2][1]);
            acc[3][0] = f2fma(d3, w0, acc[3][0]); acc[3][1] = f2fma(d3, w1, acc[3][1]);
        }
        __syncthreads();
    }
    float* __restrict__ Cd = g_xw + (size_t)d * TT * BB * GP;
    float4 bv = *(const float4*)(bs + jbase + c0);
    const int rows[4] = {r0, r0 + 1, r0 + 32, r0 + 33};
    #pragma unroll
    for (int a = 0; a < 4; a++) {
        float v0, v1, v2, v3;
        upk2(acc[a][0], v0, v1); upk2(acc[a][1], v2, v3);
        *(float4*)&Cd[(size_t)(rbase + rows[a]) * GP + jbase + c0] =
            make_float4(v0 + bv.x, v1 + bv.y, v2 + bv.z, v3 + bv.w);
    }
}

// ---------------- persistent bidirectional LSTM layer, dual-chain ----------------
// grid (13, 8): j-tile (16 units) x b-tile (16 batch). Block = 8 warps:
// warps 0-3 = forward chain, warps 4-7 = backward chain (one warp of each per SMSP,
// so one chain's barrier/memory stalls are filled by the other's FFMA2).
// Per chain per step: h-tile arrives as ONE cp.async.bulk (contiguous g_h2 slab) + mbarrier.
__global__ void __launch_bounds__(256, 1) lstm_persist(int layer) {
    const int jt = blockIdx.x, bt = blockIdx.y;
    const int tid = threadIdx.x;
    const int wid = tid >> 5, lane = tid & 31;
    const int d = wid >> 2;                  // chain / direction
    const int cw = wid & 3;                  // warp within chain
    const int c0 = cw * 16 + (lane >> 3) * 4;   // local col base (4 gates of one unit)
    const int r0 = 2 * (lane & 7);              // local batch-row pair
    const int u = jt * 16 + (c0 >> 2);          // global hidden unit
    const int jbase = jt * TJ, bbase = bt * LTB;
    const int grp = (d * 8 + bt) * 32;
    const bool leader = (tid == d * 128);
    const float* __restrict__ xwd = g_xw + (size_t)d * TT * BB * GP;
    float* __restrict__ hcat = layer ? g_hcat1 : g_hcat0;

    extern __shared__ __align__(16) float smem[];
    // layout (floats): [Ws fwd 200*64][Ws bwd 200*64][As fwd 200*16][As bwd 200*16][mbars]
    float* Ws = smem + d * (HH * TJ);
    float* As = smem + 2 * (HH * TJ) + d * (HH * LTB);
    unsigned base_u32 = (unsigned)__cvta_generic_to_shared(smem);
    unsigned as_u32 = base_u32 + (2 * (HH * TJ) + d * (HH * LTB)) * 4;
    unsigned mbar = base_u32 + (2 * (HH * TJ) + 2 * (HH * LTB)) * 4 + d * 8;

    // ---- load both directions' Whh tiles once (resident for all 512 steps)
    for (int e = tid; e < 2 * HH * 16; e += 256) {
        int dd = e / (HH * 16); int rem = e - dd * (HH * 16);
        int kk = rem >> 4, cc = (rem & 15) * 4;
        CP16(base_u32 + (unsigned)(e * 16),
             g_whht + (size_t)(layer * 2 + dd) * HH * GP + (size_t)kk * GP + jbase + cc);
    }
    CPCOMMIT; CPWAIT(0);
    if (tid == 0) {
        mbar_init(mbar, 1);          // fwd mbar (d==0 for tid 0)
        mbar_init(mbar + 8, 1);      // bwd mbar
    }
    __syncthreads();

    float cc0 = 0.f, cc1 = 0.f;      // cell state: rows r0, r0+1 of unit u
    unsigned ph = 0;

    for (int s = 0; s < TT; s++) {
        const int t = d ? (TT - 1 - s) : s;

        // prefetch xw(t): independent of h, hides DRAM/L2 latency under the wait
        const float* xwt = xwd + ((size_t)t * BB + bbase) * GP + jbase;
        float4 xa = *(const float4*)(xwt + (size_t)r0 * GP + c0);
        float4 xb = *(const float4*)(xwt + (size_t)(r0 + 1) * GP + c0);

        ull A0 = 0ull, A1 = 0ull, B0 = 0ull, B1 = 0ull;

        if (s > 0) {
            if (leader) {
                const unsigned tgt = 13u * (unsigned)s;
                unsigned v;
                do {
                    asm volatile("ld.acquire.gpu.global.u32 %0, [%1];"
                                 : "=r"(v) : "l"(g_bar + grp) : "memory");
                } while (v < tgt);
                mbar_expect_tx(mbar, HH * LTB * 4);
                bulk_g2s(as_u32, &g_h2[s & 1][d][bt][0][0], HH * LTB * 4, mbar);
            }
            mbar_wait(mbar, ph);
            ph ^= 1;

            #pragma unroll 8
            for (int kk = 0; kk < HH; kk++) {
                float2 av = *(const float2*)(As + kk * LTB + r0);
                float4 wv = *(const float4*)(Ws + kk * TJ + c0);
                ull w0 = pk2(wv.x, wv.y), w1 = pk2(wv.z, wv.w);
                ull a0 = pk2(av.x, av.x), a1 = pk2(av.y, av.y);
                A0 = f2fma(a0, w0, A0); A1 = f2fma(a0, w1, A1);
                B0 = f2fma(a1, w0, B0); B1 = f2fma(a1, w1, B1);
            }
        }

        // add xw: A* = row r0, B* = row r0+1; col pairs (i,f) and (g,o)
        A0 = f2add(A0, pk2(xa.x, xa.y)); A1 = f2add(A1, pk2(xa.z, xa.w));
        B0 = f2add(B0, pk2(xb.x, xb.y)); B1 = f2add(B1, pk2(xb.z, xb.w));

        float gi0, gf0, gg0, go0, gi1, gf1, gg1, go1;
        upk2(A0, gi0, gf0); upk2(A1, gg0, go0);
        upk2(B0, gi1, gf1); upk2(B1, gg1, go1);

        float cn0 = sigf(gf0) * cc0 + sigf(gi0) * tanhfast(gg0);
        float hn0 = sigf(go0) * tanhfast(cn0);
        float cn1 = sigf(gf1) * cc1 + sigf(gi1) * tanhfast(gg1);
        float hn1 = sigf(go1) * tanhfast(cn1);
        cc0 = cn0; cc1 = cn1;

        // publish h (group-critical), chain-barrier, release-arrive, then hcat store
        if (u < HH) {
            *(float2*)&g_h2[(s & 1) ^ 1][d][bt][u][r0] = make_float2(hn0, hn1);
        }
        asm volatile("bar.sync %0, 128;" :: "r"(1 + d) : "memory");
        if (leader) {
            asm volatile("red.release.gpu.global.add.u32 [%0], %1;"
                         :: "l"(g_bar + grp), "r"(1u) : "memory");
        }
        if (u < HH) {
            size_t hb = ((size_t)t * BB + (bbase + r0)) * (2 * HH) + d * HH + u;
            hcat[hb] = hn0;
            hcat[hb + 2 * HH] = hn1;
        }
    }
}

// ---------------- emissions: em = hcat1 @ lin_w^T + lin_b, plus exp(em) ----------------
__global__ void em_kernel(const float* __restrict__ lin_w, const float* __restrict__ lin_b) {
    int row = blockIdx.x * 8 + (threadIdx.x >> 5);
    int k = threadIdx.x & 31;
    if (k >= KK) return;
    const float4* a4 = (const float4*)(g_hcat1 + (size_t)row * (2 * HH));
    const float4* w4 = (const float4*)(lin_w + (size_t)k * (2 * HH));
    float s0 = 0, s1 = 0, s2 = 0, s3 = 0;
    #pragma unroll 4
    for (int i = 0; i < (2 * HH) / 4; i++) {
        float4 av = a4[i], wv = w4[i];
        s0 += av.x * wv.x; s1 += av.y * wv.y; s2 += av.z * wv.z; s3 += av.w * wv.w;
    }
    float acc = (s0 + s1) + (s2 + s3) + lin_b[k];
    g_em[(size_t)row * KK + k] = acc;
    g_emexp[(size_t)row * KK + k] = __expf(acc);
}

// ---------------- CRF: numerator + linear-domain forward algorithm ----------------
__global__ void crf_kernel(const int* __restrict__ y, const float* __restrict__ start,
                           const float* __restrict__ endw, const float* __restrict__ trans) {
    int b = blockIdx.x;
    int lane = threadIdx.x;
    __shared__ float Me[KK][KK];
    __shared__ float Tr[KK][KK];
    __shared__ float p[KK];
    for (int e = lane; e < KK * KK; e += 32) {
        float tv = trans[e];
        Tr[e / KK][e % KK] = tv;
        Me[e / KK][e % KK] = __expf(tv);
    }
    __syncwarp();
    float num = 0.f;
    for (int t = lane; t < TT; t += 32) {
        int yt = y[b * TT + t];
        float e = g_em[((size_t)t * BB + b) * KK + yt];
        if (t == 0) num += start[yt] + e;
        else {
            int yp = y[b * TT + t - 1];
            num += Tr[yp][yt] + e;
        }
        if (t == TT - 1) num += endw[yt];
    }
    for (int o = 16; o; o >>= 1) num += __shfl_down_sync(0xffffffffu, num, o);
    num = __shfl_sync(0xffffffffu, num, 0);
    float myp = 0.f;
    if (lane < KK) myp = __expf(start[lane] + g_em[(size_t)b * KK + lane]);
    float ssum = myp;
    for (int o = 16; o; o >>= 1) ssum += __shfl_down_sync(0xffffffffu, ssum, o);
    ssum = __shfl_sync(0xffffffffu, ssum, 0);
    float logZ = logf(ssum);
    if (lane < KK) p[lane] = myp / ssum;
    __syncwarp();
    for (int t = 1; t < TT; t++) {
        float acc = 0.f;
        if (lane < KK) {
            #pragma unroll 5
            for (int k1 = 0; k1 < KK; k1++) acc += p[k1] * Me[k1][lane];
            acc *= g_emexp[((size_t)t * BB + b) * KK + lane];
        }
        float s = acc;
        for (int o = 16; o; o >>= 1) s += __shfl_down_sync(0xffffffffu, s, o);
        s = __shfl_sync(0xffffffffu, s, 0);
        logZ += logf(s);
        float is = 1.f / s;
        __syncwarp();
        if (lane < KK) p[lane] = acc * is;
        __syncwarp();
    }
    float fin = (lane < KK) ? p[lane] * __expf(endw[lane]) : 0.f;
    for (int o = 16; o; o >>= 1) fin += __shfl_down_sync(0xffffffffu, fin, o);
    if (lane == 0) {
        float den = logZ + logf(fin);
        g_crf[b] = num - den;
    }
}

__global__ void final_reduce(float* __restrict__ out) {
    __shared__ float sm[BB];
    int tid = threadIdx.x;
    sm[tid] = g_crf[tid];
    __syncthreads();
    for (int st = 64; st > 0; st >>= 1) {
        if (tid < st) sm[tid] += sm[tid + st];
        __syncthreads();
    }
    if (tid == 0) out[0] = sm[0];
}

// ---------------- launch ----------------
extern "C" void kernel_launch(void* const* d_in, const int* in_sizes, int n_in,
                              void* d_out, int out_size) {
    const int* x = (const int*)d_in[0];
    const int* y = (const int*)d_in[1];
    // d_in[2] = mask (all ones by construction) — unused
    const float* emb = (const float*)d_in[3];
    const float* wih0 = (const float*)d_in[4];
    const float* whh0 = (const float*)d_in[5];
    const float* b0 = (const float*)d_in[6];
    const float* wih1 = (const float*)d_in[7];
    const float* whh1 = (const float*)d_in[8];
    const float* b1 = (const float*)d_in[9];
    const float* lin_w = (const float*)d_in[10];
    const float* lin_b = (const float*)d_in[11];
    const float* crf_s = (const float*)d_in[12];
    const float* crf_e = (const float*)d_in[13];
    const float* crf_t = (const float*)d_in[14];
    float* out = (float*)d_out;

    // smem: 2*Ws(200*64) + 2*As(200*16) floats + 2 mbarriers
    const int lstm_smem = (2 * HH * TJ + 2 * HH * LTB) * 4 + 32;   // 128032 bytes
    const int xw_smem = (2 * XKC * ASTR + 2 * XKC * TJ) * 4;       // 52000 bytes
    cudaFuncSetAttribute(lstm_persist, cudaFuncAttributeMaxDynamicSharedMemorySize, lstm_smem);
    cudaFuncSetAttribute(xw_gemm, cudaFuncAttributeMaxDynamicSharedMemorySize, xw_smem);

    prep_kernel<<<5538, 256>>>(b0, b1, wih0, wih1, whh0, whh1);

    // layer 0: input projection (emb gather, K=50) then persistent recurrence
    xw_gemm<<<dim3(NJT, (TT * BB) / XTB, 2), 256, xw_smem>>>(x, emb, 0);
    bar_reset<<<1, 512>>>();
    lstm_persist<<<dim3(NJT, 8), 256, lstm_smem>>>(0);

    // layer 1: input projection (K=400) then persistent recurrence
    xw_gemm<<<dim3(NJT, (TT * BB) / XTB, 2), 256, xw_smem>>>(x, emb, 1);
    bar_reset<<<1, 512>>>();
    lstm_persist<<<dim3(NJT, 8), 256, lstm_smem>>>(1);

    em_kernel<<<(TT * BB) / 8, 256>>>(lin_w, lin_b);
    crf_kernel<<<BB, 32>>>(y, crf_s, crf_e, crf_t);
    final_reduce<<<1, BB>>>(out);
}